// round 8
// baseline (speedup 1.0000x reference)
#include <cuda_runtime.h>
#include <math.h>

#define B   16
#define H   1024
#define W   1024
#define HS  512
#define WS  512
#define HC  256
#define WC  256
#define KP  32
#define CROP 160
#define NCH 32
#define CANDMAX 65536
#define SLICE 2048
#define NSLICE (CANDMAX / SLICE)   // 32

// ---- scratch (device globals; no runtime allocation allowed) ----
__device__ float g_rimg[B * HS * WS];            // 16 MB
__device__ float g_cms[B * HC * WC];             // 4 MB
__device__ unsigned long long g_cand[B * CANDMAX];
__device__ unsigned long long g_stage[B * NSLICE * KP];   // 128 KB
__device__ int   g_cnt[B];
__device__ float g_centers[B * KP * 3];          // cx, cy, validf

// ============================================================
// Stage 1: antialiased bilinear 2x downsample (jax semantics)
// ============================================================
__device__ __forceinline__ void resize_taps(int o, int n, int* idx, float* w) {
    const float wb = 0.375f / 0.875f;   // edge-renormalized
    const float ws = 0.125f / 0.875f;
    if (o == 0) {
        idx[0] = 0; w[0] = 0.0f;
        idx[1] = 0; w[1] = wb;
        idx[2] = 1; w[2] = wb;
        idx[3] = 2; w[3] = ws;
    } else if (o == n - 1) {
        idx[0] = 2 * o - 1; w[0] = ws;
        idx[1] = 2 * o;     w[1] = wb;
        idx[2] = 2 * o + 1; w[2] = wb;
        idx[3] = 2 * o + 1; w[3] = 0.0f;
    } else {
        idx[0] = 2 * o - 1; w[0] = 0.125f;
        idx[1] = 2 * o;     w[1] = 0.375f;
        idx[2] = 2 * o + 1; w[2] = 0.375f;
        idx[3] = 2 * o + 2; w[3] = 0.125f;
    }
}

__global__ void resize_kernel(const float* __restrict__ img) {
    int gid = blockIdx.x * blockDim.x + threadIdx.x;
    if (gid < B) g_cnt[gid] = 0;     // reset candidate counters each replay
    if (gid >= B * HS * WS) return;
    int b   = gid / (HS * WS);
    int rem = gid % (HS * WS);
    int oy  = rem / WS;
    int ox  = rem % WS;

    int iy[4], ix[4];
    float wy[4], wx[4];
    resize_taps(oy, HS, iy, wy);
    resize_taps(ox, WS, ix, wx);

    const float* ib = img + (long long)b * H * W;
    float acc = 0.0f;
#pragma unroll
    for (int tx = 0; tx < 4; tx++) {
        float s = 0.0f;
#pragma unroll
        for (int ty = 0; ty < 4; ty++)
            s += wy[ty] * __ldg(ib + iy[ty] * W + ix[tx]);
        acc += wx[tx] * s;
    }
    g_rimg[gid] = acc;
}

// ============================================================
// Stage 2+3 FUSED: conv1 (5x5 s2, 1->32, ReLU) + conv2 (5x5 s1,
// 32->1, sigmoid), no global h round-trip. BIT-EXACT chains.
// ============================================================
#define RTS   76
#define H2S   38
#define OFF_RT  0
#define OFF_H   5700
#define OFF_W1  16644
#define OFF_WT2 17444
#define OFF_BS  18340
#define FUSED_SMEM_FLOATS 18372
#define FUSED_SMEM_BYTES  (FUSED_SMEM_FLOATS * 4)

__global__ void fused_conv_kernel(const float* __restrict__ w1,
                                  const float* __restrict__ b1,
                                  const float* __restrict__ w2,
                                  const float* __restrict__ b2) {
    extern __shared__ __align__(16) float sm[];
    float* rt  = sm + OFF_RT;    // [75][76]
    float* hsm = sm + OFF_H;     // [8][36][38]
    float* w1s = sm + OFF_W1;    // [25][32]
    float* wt2 = sm + OFF_WT2;   // [32][28]
    float* bs1 = sm + OFF_BS;    // [32]

    int b   = blockIdx.z;
    int py0 = blockIdx.y * 32;
    int px0 = blockIdx.x * 32;
    int tid = threadIdx.x;             // 256
    int ty  = tid / 16, tx = tid % 16;
    int ly  = 2 * ty, lx = 2 * tx;

    for (int i = tid; i < 800; i += 256) w1s[i] = w1[i];
    for (int i = tid; i < 800; i += 256) {
        int c = i % 32, uv = i / 32;
        wt2[c * 28 + uv] = w2[i];
    }
    if (tid < 32) bs1[tid] = b1[tid];

    for (int i = tid; i < 75 * 75; i += 256) {
        int r = i / 75, c = i % 75;
        int gy = 2 * py0 - 5 + r;
        int gx = 2 * px0 - 5 + c;
        float v = 0.0f;
        if (gy >= 0 && gy < HS && gx >= 0 && gx < WS)
            v = g_rimg[(b * HS + gy) * WS + gx];
        rt[r * RTS + c] = v;
    }

    int off[6];
    int sidx[6];
    int val[6];
#pragma unroll
    for (int p = 0; p < 6; p++) {
        int i = tid + p * 256;
        if (i < 1296) {
            int r = i / 36, cl = i % 36;
            off[p]  = 2 * r * RTS + 2 * cl;
            sidx[p] = r * H2S + cl;
            int hy = py0 - 2 + r, hx = px0 - 2 + cl;
            val[p] = (hy >= 0 && hy < HC && hx >= 0 && hx < WC) ? 1 : 0;
        } else {
            off[p] = 0; sidx[p] = 0; val[p] = -1;
        }
    }

    float a00 = 0.f, a01 = 0.f, a10 = 0.f, a11 = 0.f;

    for (int c0 = 0; c0 < NCH; c0 += 8) {
        __syncthreads();

        float acc[6][8];
#pragma unroll
        for (int p = 0; p < 6; p++)
#pragma unroll
            for (int k = 0; k < 8; k++) acc[p][k] = 0.0f;

#pragma unroll
        for (int u = 0; u < 5; u++) {
#pragma unroll
            for (int v = 0; v < 5; v++) {
                const float4* wp = (const float4*)&w1s[(u * 5 + v) * NCH + c0];
                float4 qa = wp[0], qb = wp[1];
#pragma unroll
                for (int p = 0; p < 6; p++) {
                    if (p == 5 && val[5] < 0) continue;
                    float s = rt[off[p] + u * RTS + v];
                    acc[p][0] = fmaf(s, qa.x, acc[p][0]);
                    acc[p][1] = fmaf(s, qa.y, acc[p][1]);
                    acc[p][2] = fmaf(s, qa.z, acc[p][2]);
                    acc[p][3] = fmaf(s, qa.w, acc[p][3]);
                    acc[p][4] = fmaf(s, qb.x, acc[p][4]);
                    acc[p][5] = fmaf(s, qb.y, acc[p][5]);
                    acc[p][6] = fmaf(s, qb.z, acc[p][6]);
                    acc[p][7] = fmaf(s, qb.w, acc[p][7]);
                }
            }
        }
#pragma unroll
        for (int p = 0; p < 6; p++) {
            if (val[p] < 0) continue;
#pragma unroll
            for (int k = 0; k < 8; k++) {
                float hv = 0.0f;
                if (val[p]) {
                    hv = acc[p][k] + bs1[c0 + k];
                    hv = hv > 0.0f ? hv : 0.0f;
                }
                hsm[k * (36 * H2S) + sidx[p]] = hv;
            }
        }
        __syncthreads();

#pragma unroll
        for (int cc = 0; cc < 8; cc++) {
            int c = c0 + cc;
            float w[25];
            const float4* wp = (const float4*)&wt2[c * 28];
            {
                float4 q0 = wp[0], q1 = wp[1], q2 = wp[2];
                float4 q3 = wp[3], q4 = wp[4], q5 = wp[5];
                w[0]=q0.x; w[1]=q0.y; w[2]=q0.z; w[3]=q0.w;
                w[4]=q1.x; w[5]=q1.y; w[6]=q1.z; w[7]=q1.w;
                w[8]=q2.x; w[9]=q2.y; w[10]=q2.z; w[11]=q2.w;
                w[12]=q3.x; w[13]=q3.y; w[14]=q3.z; w[15]=q3.w;
                w[16]=q4.x; w[17]=q4.y; w[18]=q4.z; w[19]=q4.w;
                w[20]=q5.x; w[21]=q5.y; w[22]=q5.z; w[23]=q5.w;
                w[24] = wt2[c * 28 + 24];
            }
#pragma unroll
            for (int u = 0; u < 6; u++) {
                const float* hp = &hsm[(cc * 36 + ly + u) * H2S + lx];
                float2 p0 = *(const float2*)(hp);
                float2 p1 = *(const float2*)(hp + 2);
                float2 p2 = *(const float2*)(hp + 4);
                float v0 = p0.x, v1 = p0.y, v2 = p1.x;
                float v3 = p1.y, v4 = p2.x, v5 = p2.y;
                if (u < 5) {
                    const int o = u * 5;
                    a00 = fmaf(v0, w[o+0], a00); a00 = fmaf(v1, w[o+1], a00);
                    a00 = fmaf(v2, w[o+2], a00); a00 = fmaf(v3, w[o+3], a00);
                    a00 = fmaf(v4, w[o+4], a00);
                    a01 = fmaf(v1, w[o+0], a01); a01 = fmaf(v2, w[o+1], a01);
                    a01 = fmaf(v3, w[o+2], a01); a01 = fmaf(v4, w[o+3], a01);
                    a01 = fmaf(v5, w[o+4], a01);
                }
                if (u > 0) {
                    const int o = (u - 1) * 5;
                    a10 = fmaf(v0, w[o+0], a10); a10 = fmaf(v1, w[o+1], a10);
                    a10 = fmaf(v2, w[o+2], a10); a10 = fmaf(v3, w[o+3], a10);
                    a10 = fmaf(v4, w[o+4], a10);
                    a11 = fmaf(v1, w[o+0], a11); a11 = fmaf(v2, w[o+1], a11);
                    a11 = fmaf(v3, w[o+2], a11); a11 = fmaf(v4, w[o+3], a11);
                    a11 = fmaf(v5, w[o+4], a11);
                }
            }
        }
    }

    float bias = __ldg(b2);
    int oy = py0 + ly, ox = px0 + lx;
    g_cms[(b * HC + oy    ) * WC + ox    ] = 1.0f / (1.0f + expf(-(a00 + bias)));
    g_cms[(b * HC + oy    ) * WC + ox + 1] = 1.0f / (1.0f + expf(-(a01 + bias)));
    g_cms[(b * HC + oy + 1) * WC + ox    ] = 1.0f / (1.0f + expf(-(a10 + bias)));
    g_cms[(b * HC + oy + 1) * WC + ox + 1] = 1.0f / (1.0f + expf(-(a11 + bias)));
}

// ============================================================
// Stage 4: tiled 3x3 NMS + threshold -> packed candidates
// ============================================================
__global__ void nms_kernel() {
    __shared__ float t[18 * 18];
    __shared__ int cnt_s;
    __shared__ int base_s;

    int b   = blockIdx.z;
    int py0 = blockIdx.y * 16;
    int px0 = blockIdx.x * 16;
    int tid = threadIdx.x;
    int ty  = tid / 16, tx = tid % 16;

    if (tid == 0) cnt_s = 0;
    for (int i = tid; i < 18 * 18; i += 256) {
        int r = i / 18, c = i % 18;
        int gy = py0 - 1 + r;
        int gx = px0 - 1 + c;
        float v = -1.0f;
        if (gy >= 0 && gy < HC && gx >= 0 && gx < WC)
            v = g_cms[(b * HC + gy) * WC + gx];
        t[i] = v;
    }
    __syncthreads();

    float v = t[(ty + 1) * 18 + (tx + 1)];
    bool ok = (v > 0.2f);
    if (ok) {
#pragma unroll
        for (int dy = -1; dy <= 1; dy++)
#pragma unroll
            for (int dx = -1; dx <= 1; dx++) {
                if (dy == 0 && dx == 0) continue;
                if (t[(ty + 1 + dy) * 18 + (tx + 1 + dx)] > v) ok = false;
            }
    }
    int pos = -1;
    if (ok) pos = atomicAdd(&cnt_s, 1);
    __syncthreads();
    if (tid == 0 && cnt_s > 0) base_s = atomicAdd(&g_cnt[b], cnt_s);
    __syncthreads();
    if (ok) {
        unsigned int rem = (unsigned int)((py0 + ty) * WC + (px0 + tx));
        unsigned int fb = __float_as_uint(v);
        unsigned long long key = ((unsigned long long)fb << 32) | (~rem);
        g_cand[b * CANDMAX + base_s + pos] = key;
    }
}

// ============================================================
// Stage 5a: per-slice top-32 via smem bitonic sort (descending).
// Keys unique u64 -> selection & order bit-identical to global
// max-extraction (= jax top_k order).
// ============================================================
__global__ void topkA_kernel() {
    __shared__ unsigned long long s[SLICE];
    int b     = blockIdx.y;
    int slice = blockIdx.x;
    int tid   = threadIdx.x;   // 256

    int n = g_cnt[b];
    if (n > CANDMAX) n = CANDMAX;
    int start = slice * SLICE;
    int m = n - start;
    if (m < 0) m = 0;
    if (m > SLICE) m = SLICE;

    unsigned long long* dst = &g_stage[(b * NSLICE + slice) * KP];
    if (m == 0) {
        if (tid < KP) dst[tid] = 0ULL;
        return;
    }

    int N = 1;
    while (N < m) N <<= 1;

    for (int i = tid; i < N; i += 256)
        s[i] = (i < m) ? g_cand[b * CANDMAX + start + i] : 0ULL;
    __syncthreads();

    for (int k = 2; k <= N; k <<= 1) {
        for (int j = k >> 1; j > 0; j >>= 1) {
            for (int idx = tid; idx < N; idx += 256) {
                int p = idx ^ j;
                if (p > idx) {
                    unsigned long long a = s[idx], c = s[p];
                    bool up = ((idx & k) == 0);   // up => larger stays at idx
                    if ((a < c) == up) { s[idx] = c; s[p] = a; }
                }
            }
            __syncthreads();
        }
    }
    if (tid < KP) dst[tid] = s[tid];
}

// ============================================================
// Stage 5b: merge 32 slice-tops (1024 keys), final top-32 +
// integral refinement (5x5 patch). Refinement unchanged.
// ============================================================
__global__ void topkB_kernel(float* __restrict__ out_offs,
                             float* __restrict__ out_vals,
                             float* __restrict__ out_valid) {
    __shared__ unsigned long long s[NSLICE * KP];   // 1024
    const int N = NSLICE * KP;
    int b = blockIdx.x;
    int tid = threadIdx.x;   // 256

    for (int i = tid; i < N; i += 256)
        s[i] = g_stage[b * N + i];
    __syncthreads();

    for (int k = 2; k <= N; k <<= 1) {
        for (int j = k >> 1; j > 0; j >>= 1) {
            for (int idx = tid; idx < N; idx += 256) {
                int p = idx ^ j;
                if (p > idx) {
                    unsigned long long a = s[idx], c = s[p];
                    bool up = ((idx & k) == 0);
                    if ((a < c) == up) { s[idx] = c; s[p] = a; }
                }
            }
            __syncthreads();
        }
    }

    // --- refinement: thread k processes peak k (unchanged) ---
    if (tid < KP) {
        int k = tid;
        unsigned long long key = s[k];
        float cx = 80.0f, cy = 80.0f, val = 0.0f, vf = 0.0f;
        float offx = 0.0f, offy = 0.0f;
        if (key != 0ULL) {
            vf = 1.0f;
            unsigned int idx = ~(unsigned int)(key & 0xFFFFFFFFULL);
            val = __uint_as_float((unsigned int)(key >> 32));
            int py = idx / WC, px = idx % WC;
            float sum = 0.0f, sx = 0.0f, sy = 0.0f;
            for (int dy = -2; dy <= 2; dy++) {
                for (int dx = -2; dx <= 2; dx++) {
                    int yy = py + dy, xx = px + dx;
                    if (yy >= 0 && yy < HC && xx >= 0 && xx < WC) {
                        float pv = g_cms[(b * HC + yy) * WC + xx];
                        sum += pv;
                        sx += pv * (float)dx;
                        sy += pv * (float)dy;
                    }
                }
            }
            float g = sum + 1e-12f;
            float dxo = sx / g;
            float dyo = sy / g;
            cx = ((float)px + dxo) * 2.0f / 0.5f;
            cy = ((float)py + dyo) * 2.0f / 0.5f;
            offx = cx - 80.0f;
            offy = cy - 80.0f;
        }
        out_vals[b * KP + k] = val;
        out_valid[b * KP + k] = vf;
        out_offs[(b * KP + k) * 2 + 0] = offx;
        out_offs[(b * KP + k) * 2 + 1] = offy;
        g_centers[(b * KP + k) * 3 + 0] = cx;
        g_centers[(b * KP + k) * 3 + 1] = cy;
        g_centers[(b * KP + k) * 3 + 2] = vf;
    }
}

// ============================================================
// Stage 6: bilinear 160x160 crops from full image
// ============================================================
__global__ void crop_kernel(const float* __restrict__ img, float* __restrict__ out) {
    int b = blockIdx.z, k = blockIdx.y, i = blockIdx.x;
    int j = threadIdx.x;

    float cx = g_centers[(b * KP + k) * 3 + 0];
    float cy = g_centers[(b * KP + k) * 3 + 1];
    float vf = g_centers[(b * KP + k) * 3 + 2];

    float sy = (cy - 79.5f) + (float)i;
    float sx = (cx - 79.5f) + (float)j;
    float y0 = floorf(sy), x0 = floorf(sx);
    float wy = sy - y0, wx = sx - x0;
    int y0i = (int)y0, x0i = (int)x0;
    int yi0 = min(max(y0i, 0), H - 1);
    int yi1 = min(max(y0i + 1, 0), H - 1);
    int xi0 = min(max(x0i, 0), W - 1);
    int xi1 = min(max(x0i + 1, 0), W - 1);

    const float* ib = img + (long long)b * H * W;
    float v00 = __ldg(ib + yi0 * W + xi0);
    float v01 = __ldg(ib + yi0 * W + xi1);
    float v10 = __ldg(ib + yi1 * W + xi0);
    float v11 = __ldg(ib + yi1 * W + xi1);

    float top = v00 * (1.0f - wx) + v01 * wx;
    float bot = v10 * (1.0f - wx) + v11 * wx;
    float val = top * (1.0f - wy) + bot * wy;

    float inr = (sy >= 0.0f && sy <= (float)(H - 1) &&
                 sx >= 0.0f && sx <= (float)(W - 1)) ? 1.0f : 0.0f;

    out[(((long long)(b * KP + k)) * CROP + i) * CROP + j] = val * inr * vf;
}

// ============================================================
extern "C" void kernel_launch(void* const* d_in, const int* in_sizes, int n_in,
                              void* d_out, int out_size) {
    const float* img = (const float*)d_in[0];
    const float* w1  = (const float*)d_in[1];
    const float* b1  = (const float*)d_in[2];
    const float* w2  = (const float*)d_in[3];
    const float* b2  = (const float*)d_in[4];

    float* out = (float*)d_out;
    float* out_crops = out;
    float* out_offs  = out + (long long)B * KP * CROP * CROP;
    float* out_vals  = out_offs + B * KP * 2;
    float* out_valid = out_vals + B * KP;

    cudaFuncSetAttribute(fused_conv_kernel,
                         cudaFuncAttributeMaxDynamicSharedMemorySize,
                         FUSED_SMEM_BYTES);

    int n1 = B * HS * WS;
    resize_kernel<<<(n1 + 255) / 256, 256>>>(img);

    dim3 gconv(WC / 32, HC / 32, B);
    fused_conv_kernel<<<gconv, 256, FUSED_SMEM_BYTES>>>(w1, b1, w2, b2);

    dim3 gnms(WC / 16, HC / 16, B);
    nms_kernel<<<gnms, 256>>>();

    dim3 gtopa(NSLICE, B);
    topkA_kernel<<<gtopa, 256>>>();
    topkB_kernel<<<B, 256>>>(out_offs, out_vals, out_valid);

    dim3 gcrop(CROP, KP, B);
    crop_kernel<<<gcrop, CROP>>>(img, out_crops);
}

// round 16
// speedup vs baseline: 1.2032x; 1.2032x over previous
#include <cuda_runtime.h>
#include <math.h>

#define B   16
#define H   1024
#define W   1024
#define HS  512
#define WS  512
#define HC  256
#define WC  256
#define KP  32
#define CROP 160
#define NCH 32
#define CANDMAX 65536
#define SLICE 2048
#define NSLICE (CANDMAX / SLICE)   // 32

// ---- scratch (device globals; no runtime allocation allowed) ----
__device__ float g_rimg[B * HS * WS];            // 16 MB
__device__ float g_cms[B * HC * WC];             // 4 MB
__device__ unsigned long long g_cand[B * CANDMAX];
__device__ unsigned long long g_stage[B * NSLICE * KP];   // 128 KB
__device__ int   g_cnt[B];
__device__ float g_centers[B * KP * 3];          // cx, cy, validf

// ============================================================
// Stage 1: antialiased bilinear 2x downsample (jax semantics)
// ============================================================
__device__ __forceinline__ void resize_taps(int o, int n, int* idx, float* w) {
    const float wb = 0.375f / 0.875f;   // edge-renormalized
    const float ws = 0.125f / 0.875f;
    if (o == 0) {
        idx[0] = 0; w[0] = 0.0f;
        idx[1] = 0; w[1] = wb;
        idx[2] = 1; w[2] = wb;
        idx[3] = 2; w[3] = ws;
    } else if (o == n - 1) {
        idx[0] = 2 * o - 1; w[0] = ws;
        idx[1] = 2 * o;     w[1] = wb;
        idx[2] = 2 * o + 1; w[2] = wb;
        idx[3] = 2 * o + 1; w[3] = 0.0f;
    } else {
        idx[0] = 2 * o - 1; w[0] = 0.125f;
        idx[1] = 2 * o;     w[1] = 0.375f;
        idx[2] = 2 * o + 1; w[2] = 0.375f;
        idx[3] = 2 * o + 2; w[3] = 0.125f;
    }
}

__global__ void resize_kernel(const float* __restrict__ img) {
    int gid = blockIdx.x * blockDim.x + threadIdx.x;
    if (gid < B) g_cnt[gid] = 0;     // reset candidate counters each replay
    if (gid >= B * HS * WS) return;
    int b   = gid / (HS * WS);
    int rem = gid % (HS * WS);
    int oy  = rem / WS;
    int ox  = rem % WS;

    int iy[4], ix[4];
    float wy[4], wx[4];
    resize_taps(oy, HS, iy, wy);
    resize_taps(ox, WS, ix, wx);

    const float* ib = img + (long long)b * H * W;
    float acc = 0.0f;
#pragma unroll
    for (int tx = 0; tx < 4; tx++) {
        float s = 0.0f;
#pragma unroll
        for (int ty = 0; ty < 4; ty++)
            s += wy[ty] * __ldg(ib + iy[ty] * W + ix[tx]);
        acc += wx[tx] * s;
    }
    g_rimg[gid] = acc;
}

// ============================================================
// Stage 2+3 FUSED: conv1 (5x5 s2, 1->32, ReLU) + conv2 (5x5 s1,
// 32->1, sigmoid), no global h round-trip. BIT-EXACT chains.
// ============================================================
#define RTS   76
#define H2S   38
#define OFF_RT  0
#define OFF_H   5700
#define OFF_W1  16644
#define OFF_WT2 17444
#define OFF_BS  18340
#define FUSED_SMEM_FLOATS 18372
#define FUSED_SMEM_BYTES  (FUSED_SMEM_FLOATS * 4)

__global__ void fused_conv_kernel(const float* __restrict__ w1,
                                  const float* __restrict__ b1,
                                  const float* __restrict__ w2,
                                  const float* __restrict__ b2) {
    extern __shared__ __align__(16) float sm[];
    float* rt  = sm + OFF_RT;    // [75][76]
    float* hsm = sm + OFF_H;     // [8][36][38]
    float* w1s = sm + OFF_W1;    // [25][32]
    float* wt2 = sm + OFF_WT2;   // [32][28]
    float* bs1 = sm + OFF_BS;    // [32]

    int b   = blockIdx.z;
    int py0 = blockIdx.y * 32;
    int px0 = blockIdx.x * 32;
    int tid = threadIdx.x;             // 256
    int ty  = tid / 16, tx = tid % 16;
    int ly  = 2 * ty, lx = 2 * tx;

    for (int i = tid; i < 800; i += 256) w1s[i] = w1[i];
    for (int i = tid; i < 800; i += 256) {
        int c = i % 32, uv = i / 32;
        wt2[c * 28 + uv] = w2[i];
    }
    if (tid < 32) bs1[tid] = b1[tid];

    for (int i = tid; i < 75 * 75; i += 256) {
        int r = i / 75, c = i % 75;
        int gy = 2 * py0 - 5 + r;
        int gx = 2 * px0 - 5 + c;
        float v = 0.0f;
        if (gy >= 0 && gy < HS && gx >= 0 && gx < WS)
            v = g_rimg[(b * HS + gy) * WS + gx];
        rt[r * RTS + c] = v;
    }

    int off[6];
    int sidx[6];
    int val[6];
#pragma unroll
    for (int p = 0; p < 6; p++) {
        int i = tid + p * 256;
        if (i < 1296) {
            int r = i / 36, cl = i % 36;
            off[p]  = 2 * r * RTS + 2 * cl;
            sidx[p] = r * H2S + cl;
            int hy = py0 - 2 + r, hx = px0 - 2 + cl;
            val[p] = (hy >= 0 && hy < HC && hx >= 0 && hx < WC) ? 1 : 0;
        } else {
            off[p] = 0; sidx[p] = 0; val[p] = -1;
        }
    }

    float a00 = 0.f, a01 = 0.f, a10 = 0.f, a11 = 0.f;

    for (int c0 = 0; c0 < NCH; c0 += 8) {
        __syncthreads();

        float acc[6][8];
#pragma unroll
        for (int p = 0; p < 6; p++)
#pragma unroll
            for (int k = 0; k < 8; k++) acc[p][k] = 0.0f;

#pragma unroll
        for (int u = 0; u < 5; u++) {
#pragma unroll
            for (int v = 0; v < 5; v++) {
                const float4* wp = (const float4*)&w1s[(u * 5 + v) * NCH + c0];
                float4 qa = wp[0], qb = wp[1];
#pragma unroll
                for (int p = 0; p < 6; p++) {
                    if (p == 5 && val[5] < 0) continue;
                    float s = rt[off[p] + u * RTS + v];
                    acc[p][0] = fmaf(s, qa.x, acc[p][0]);
                    acc[p][1] = fmaf(s, qa.y, acc[p][1]);
                    acc[p][2] = fmaf(s, qa.z, acc[p][2]);
                    acc[p][3] = fmaf(s, qa.w, acc[p][3]);
                    acc[p][4] = fmaf(s, qb.x, acc[p][4]);
                    acc[p][5] = fmaf(s, qb.y, acc[p][5]);
                    acc[p][6] = fmaf(s, qb.z, acc[p][6]);
                    acc[p][7] = fmaf(s, qb.w, acc[p][7]);
                }
            }
        }
#pragma unroll
        for (int p = 0; p < 6; p++) {
            if (val[p] < 0) continue;
#pragma unroll
            for (int k = 0; k < 8; k++) {
                float hv = 0.0f;
                if (val[p]) {
                    hv = acc[p][k] + bs1[c0 + k];
                    hv = hv > 0.0f ? hv : 0.0f;
                }
                hsm[k * (36 * H2S) + sidx[p]] = hv;
            }
        }
        __syncthreads();

#pragma unroll
        for (int cc = 0; cc < 8; cc++) {
            int c = c0 + cc;
            float w[25];
            const float4* wp = (const float4*)&wt2[c * 28];
            {
                float4 q0 = wp[0], q1 = wp[1], q2 = wp[2];
                float4 q3 = wp[3], q4 = wp[4], q5 = wp[5];
                w[0]=q0.x; w[1]=q0.y; w[2]=q0.z; w[3]=q0.w;
                w[4]=q1.x; w[5]=q1.y; w[6]=q1.z; w[7]=q1.w;
                w[8]=q2.x; w[9]=q2.y; w[10]=q2.z; w[11]=q2.w;
                w[12]=q3.x; w[13]=q3.y; w[14]=q3.z; w[15]=q3.w;
                w[16]=q4.x; w[17]=q4.y; w[18]=q4.z; w[19]=q4.w;
                w[20]=q5.x; w[21]=q5.y; w[22]=q5.z; w[23]=q5.w;
                w[24] = wt2[c * 28 + 24];
            }
#pragma unroll
            for (int u = 0; u < 6; u++) {
                const float* hp = &hsm[(cc * 36 + ly + u) * H2S + lx];
                float2 p0 = *(const float2*)(hp);
                float2 p1 = *(const float2*)(hp + 2);
                float2 p2 = *(const float2*)(hp + 4);
                float v0 = p0.x, v1 = p0.y, v2 = p1.x;
                float v3 = p1.y, v4 = p2.x, v5 = p2.y;
                if (u < 5) {
                    const int o = u * 5;
                    a00 = fmaf(v0, w[o+0], a00); a00 = fmaf(v1, w[o+1], a00);
                    a00 = fmaf(v2, w[o+2], a00); a00 = fmaf(v3, w[o+3], a00);
                    a00 = fmaf(v4, w[o+4], a00);
                    a01 = fmaf(v1, w[o+0], a01); a01 = fmaf(v2, w[o+1], a01);
                    a01 = fmaf(v3, w[o+2], a01); a01 = fmaf(v4, w[o+3], a01);
                    a01 = fmaf(v5, w[o+4], a01);
                }
                if (u > 0) {
                    const int o = (u - 1) * 5;
                    a10 = fmaf(v0, w[o+0], a10); a10 = fmaf(v1, w[o+1], a10);
                    a10 = fmaf(v2, w[o+2], a10); a10 = fmaf(v3, w[o+3], a10);
                    a10 = fmaf(v4, w[o+4], a10);
                    a11 = fmaf(v1, w[o+0], a11); a11 = fmaf(v2, w[o+1], a11);
                    a11 = fmaf(v3, w[o+2], a11); a11 = fmaf(v4, w[o+3], a11);
                    a11 = fmaf(v5, w[o+4], a11);
                }
            }
        }
    }

    float bias = __ldg(b2);
    int oy = py0 + ly, ox = px0 + lx;
    g_cms[(b * HC + oy    ) * WC + ox    ] = 1.0f / (1.0f + expf(-(a00 + bias)));
    g_cms[(b * HC + oy    ) * WC + ox + 1] = 1.0f / (1.0f + expf(-(a01 + bias)));
    g_cms[(b * HC + oy + 1) * WC + ox    ] = 1.0f / (1.0f + expf(-(a10 + bias)));
    g_cms[(b * HC + oy + 1) * WC + ox + 1] = 1.0f / (1.0f + expf(-(a11 + bias)));
}

// ============================================================
// Stage 4: tiled 3x3 NMS + threshold -> packed candidates
// ============================================================
__global__ void nms_kernel() {
    __shared__ float t[18 * 18];
    __shared__ int cnt_s;
    __shared__ int base_s;

    int b   = blockIdx.z;
    int py0 = blockIdx.y * 16;
    int px0 = blockIdx.x * 16;
    int tid = threadIdx.x;
    int ty  = tid / 16, tx = tid % 16;

    if (tid == 0) cnt_s = 0;
    for (int i = tid; i < 18 * 18; i += 256) {
        int r = i / 18, c = i % 18;
        int gy = py0 - 1 + r;
        int gx = px0 - 1 + c;
        float v = -1.0f;
        if (gy >= 0 && gy < HC && gx >= 0 && gx < WC)
            v = g_cms[(b * HC + gy) * WC + gx];
        t[i] = v;
    }
    __syncthreads();

    float v = t[(ty + 1) * 18 + (tx + 1)];
    bool ok = (v > 0.2f);
    if (ok) {
#pragma unroll
        for (int dy = -1; dy <= 1; dy++)
#pragma unroll
            for (int dx = -1; dx <= 1; dx++) {
                if (dy == 0 && dx == 0) continue;
                if (t[(ty + 1 + dy) * 18 + (tx + 1 + dx)] > v) ok = false;
            }
    }
    int pos = -1;
    if (ok) pos = atomicAdd(&cnt_s, 1);
    __syncthreads();
    if (tid == 0 && cnt_s > 0) base_s = atomicAdd(&g_cnt[b], cnt_s);
    __syncthreads();
    if (ok) {
        unsigned int rem = (unsigned int)((py0 + ty) * WC + (px0 + tx));
        unsigned int fb = __float_as_uint(v);
        unsigned long long key = ((unsigned long long)fb << 32) | (~rem);
        g_cand[b * CANDMAX + base_s + pos] = key;
    }
}

// ============================================================
// Warp-level sorted-32 primitives (u64 keys, descending, exact)
// ============================================================
__device__ __forceinline__ unsigned long long sort32_desc(unsigned long long key, int lane) {
#pragma unroll
    for (int k = 2; k <= 32; k <<= 1) {
#pragma unroll
        for (int j = k >> 1; j > 0; j >>= 1) {
            unsigned long long other = __shfl_xor_sync(0xffffffffu, key, j);
            bool dirDesc = ((lane & k) == 0);
            bool lower   = ((lane & j) == 0);
            bool keepMax = (lower == dirDesc);
            bool less    = key < other;
            key = (less == keepMax) ? other : key;
        }
    }
    return key;
}

// a, b sorted descending; returns top-32 of union, sorted descending.
__device__ __forceinline__ unsigned long long merge_top32(unsigned long long a, unsigned long long b, int lane) {
    unsigned long long br = __shfl_sync(0xffffffffu, b, 31 - lane);
    unsigned long long t  = (a > br) ? a : br;   // bitonic
#pragma unroll
    for (int j = 16; j > 0; j >>= 1) {
        unsigned long long other = __shfl_xor_sync(0xffffffffu, t, j);
        bool lower = ((lane & j) == 0);
        bool less  = t < other;
        t = (less == lower) ? other : t;         // lower lane keeps max
    }
    return t;
}

// ============================================================
// Stage 5a: per-slice top-32 via register warp-sort (no smem sort)
// ============================================================
__global__ void topkA_kernel() {
    __shared__ unsigned long long warptop[8 * KP];
    int b     = blockIdx.y;
    int slice = blockIdx.x;
    int tid   = threadIdx.x;   // 256
    int lane  = tid & 31, w = tid >> 5;

    int n = g_cnt[b];
    if (n > CANDMAX) n = CANDMAX;
    int start = slice * SLICE;
    int m = n - start;
    if (m > SLICE) m = SLICE;

    unsigned long long* dst = &g_stage[(b * NSLICE + slice) * KP];
    if (m <= 0) {
        if (tid < KP) dst[tid] = 0ULL;
        return;
    }
    const unsigned long long* src = &g_cand[b * CANDMAX + start];

    const int CHUNK = SLICE / 8;   // 256 keys per warp
    int base = w * CHUNK;
    unsigned long long run = 0ULL;
    if (base < m) {
        int i = base + lane;
        run = sort32_desc((i < m) ? src[i] : 0ULL, lane);
#pragma unroll
        for (int g = 1; g < CHUNK / 32; g++) {
            int ii = base + g * 32 + lane;
            if (base + g * 32 >= m) break;
            unsigned long long key = sort32_desc((ii < m) ? src[ii] : 0ULL, lane);
            run = merge_top32(run, key, lane);
        }
    }
    warptop[w * KP + lane] = run;
    __syncthreads();

    if (w == 0) {
        unsigned long long acc = warptop[lane];
#pragma unroll
        for (int l = 1; l < 8; l++)
            acc = merge_top32(acc, warptop[l * KP + lane], lane);
        dst[lane] = acc;
    }
}

// ============================================================
// Stage 5b: merge 32 sorted slice-tops -> final top-32 +
// integral refinement (5x5 patch, unchanged).
// ============================================================
__global__ void topkB_kernel(float* __restrict__ out_offs,
                             float* __restrict__ out_vals,
                             float* __restrict__ out_valid) {
    __shared__ unsigned long long warptop[8 * KP];
    __shared__ unsigned long long fin[KP];
    int b = blockIdx.x;
    int tid = threadIdx.x;   // 256
    int lane = tid & 31, w = tid >> 5;

    const unsigned long long* src = &g_stage[b * NSLICE * KP];
    // warp w merges sorted lists 4w..4w+3
    unsigned long long acc = src[(4 * w) * KP + lane];
#pragma unroll
    for (int l = 1; l < 4; l++)
        acc = merge_top32(acc, src[(4 * w + l) * KP + lane], lane);
    warptop[w * KP + lane] = acc;
    __syncthreads();

    if (w == 0) {
        unsigned long long a = warptop[lane];
#pragma unroll
        for (int l = 1; l < 8; l++)
            a = merge_top32(a, warptop[l * KP + lane], lane);
        fin[lane] = a;
    }
    __syncthreads();

    // --- refinement: thread k processes peak k (unchanged) ---
    if (tid < KP) {
        int k = tid;
        unsigned long long key = fin[k];
        float cx = 80.0f, cy = 80.0f, val = 0.0f, vf = 0.0f;
        float offx = 0.0f, offy = 0.0f;
        if (key != 0ULL) {
            vf = 1.0f;
            unsigned int idx = ~(unsigned int)(key & 0xFFFFFFFFULL);
            val = __uint_as_float((unsigned int)(key >> 32));
            int py = idx / WC, px = idx % WC;
            float sum = 0.0f, sx = 0.0f, sy = 0.0f;
            for (int dy = -2; dy <= 2; dy++) {
                for (int dx = -2; dx <= 2; dx++) {
                    int yy = py + dy, xx = px + dx;
                    if (yy >= 0 && yy < HC && xx >= 0 && xx < WC) {
                        float pv = g_cms[(b * HC + yy) * WC + xx];
                        sum += pv;
                        sx += pv * (float)dx;
                        sy += pv * (float)dy;
                    }
                }
            }
            float g = sum + 1e-12f;
            float dxo = sx / g;
            float dyo = sy / g;
            cx = ((float)px + dxo) * 2.0f / 0.5f;
            cy = ((float)py + dyo) * 2.0f / 0.5f;
            offx = cx - 80.0f;
            offy = cy - 80.0f;
        }
        out_vals[b * KP + k] = val;
        out_valid[b * KP + k] = vf;
        out_offs[(b * KP + k) * 2 + 0] = offx;
        out_offs[(b * KP + k) * 2 + 1] = offy;
        g_centers[(b * KP + k) * 3 + 0] = cx;
        g_centers[(b * KP + k) * 3 + 1] = cy;
        g_centers[(b * KP + k) * 3 + 2] = vf;
    }
}

// ============================================================
// Stage 6: bilinear 160x160 crops from full image
// ============================================================
__global__ void crop_kernel(const float* __restrict__ img, float* __restrict__ out) {
    int b = blockIdx.z, k = blockIdx.y, i = blockIdx.x;
    int j = threadIdx.x;

    float cx = g_centers[(b * KP + k) * 3 + 0];
    float cy = g_centers[(b * KP + k) * 3 + 1];
    float vf = g_centers[(b * KP + k) * 3 + 2];

    float sy = (cy - 79.5f) + (float)i;
    float sx = (cx - 79.5f) + (float)j;
    float y0 = floorf(sy), x0 = floorf(sx);
    float wy = sy - y0, wx = sx - x0;
    int y0i = (int)y0, x0i = (int)x0;
    int yi0 = min(max(y0i, 0), H - 1);
    int yi1 = min(max(y0i + 1, 0), H - 1);
    int xi0 = min(max(x0i, 0), W - 1);
    int xi1 = min(max(x0i + 1, 0), W - 1);

    const float* ib = img + (long long)b * H * W;
    float v00 = __ldg(ib + yi0 * W + xi0);
    float v01 = __ldg(ib + yi0 * W + xi1);
    float v10 = __ldg(ib + yi1 * W + xi0);
    float v11 = __ldg(ib + yi1 * W + xi1);

    float top = v00 * (1.0f - wx) + v01 * wx;
    float bot = v10 * (1.0f - wx) + v11 * wx;
    float val = top * (1.0f - wy) + bot * wy;

    float inr = (sy >= 0.0f && sy <= (float)(H - 1) &&
                 sx >= 0.0f && sx <= (float)(W - 1)) ? 1.0f : 0.0f;

    out[(((long long)(b * KP + k)) * CROP + i) * CROP + j] = val * inr * vf;
}

// ============================================================
extern "C" void kernel_launch(void* const* d_in, const int* in_sizes, int n_in,
                              void* d_out, int out_size) {
    const float* img = (const float*)d_in[0];
    const float* w1  = (const float*)d_in[1];
    const float* b1  = (const float*)d_in[2];
    const float* w2  = (const float*)d_in[3];
    const float* b2  = (const float*)d_in[4];

    float* out = (float*)d_out;
    float* out_crops = out;
    float* out_offs  = out + (long long)B * KP * CROP * CROP;
    float* out_vals  = out_offs + B * KP * 2;
    float* out_valid = out_vals + B * KP;

    cudaFuncSetAttribute(fused_conv_kernel,
                         cudaFuncAttributeMaxDynamicSharedMemorySize,
                         FUSED_SMEM_BYTES);

    int n1 = B * HS * WS;
    resize_kernel<<<(n1 + 255) / 256, 256>>>(img);

    dim3 gconv(WC / 32, HC / 32, B);
    fused_conv_kernel<<<gconv, 256, FUSED_SMEM_BYTES>>>(w1, b1, w2, b2);

    dim3 gnms(WC / 16, HC / 16, B);
    nms_kernel<<<gnms, 256>>>();

    dim3 gtopa(NSLICE, B);
    topkA_kernel<<<gtopa, 256>>>();
    topkB_kernel<<<B, 256>>>(out_offs, out_vals, out_valid);

    dim3 gcrop(CROP, KP, B);
    crop_kernel<<<gcrop, CROP>>>(img, out_crops);
}